// round 13
// baseline (speedup 1.0000x reference)
#include <cuda_runtime.h>
#include <cuda_fp16.h>
#include <cuda_pipeline.h>
#include <cstdint>

#define NN   4096
#define EE   8
#define HH   128
#define MAXW 96
#define MSGW (2*EE*HH)   /* 2048 */
#define G3   384
#define TSTEPS 4

// ----------------------------------------------------------------------------
// Device-global scratch (allocation-free contract; zero-initialized at load)
// ----------------------------------------------------------------------------
__device__ int    g_cnt_raw[2*EE*NN];    // build target; re-zeroed by sort
__device__ int    g_cnt    [2*EE*NN];    // clamped counts for spmm
__device__ int    g_ell_out[EE*NN*MAXW];
__device__ int    g_ell_in [EE*NN*MAXW];
__device__ __half g_hs16  [NN*MSGW];     // [n][dir*1024 + e*128 + h]
__device__ __half g_msg16 [NN*MSGW];
__device__ __half g_h16   [NN*HH];
__device__ __half g_Wcat16[MSGW*HH];
__device__ __half g_Wx16  [G3*MSGW];
__device__ __half g_Wh16  [G3*HH];
__device__ float  g_bcat  [MSGW];
__device__ float  g_gx    [4*NN*G3];     // split-K=4 partial buffers
__device__ float  g_gh    [NN*G3];
__device__ float  g_ipart [4*NN*128];    // init GEMM split-K partials
__device__ float  g_init  [NN*144];

// ----------------------------------------------------------------------------
// Fused build + weight-prep (both low-register memory-bound roles).
// ----------------------------------------------------------------------------
#define N_WCAT (EE*HH*HH)
#define N_WX   (G3*MSGW)
#define N_WH   (G3*HH)
#define PREP_TOTAL (2*N_WCAT + N_WX + N_WH + MSGW)
#define BUILD_BLOCKS (EE * NN * (NN / 4) / 256)       /* 131072 */
#define PREP_BLOCKS  ((PREP_TOTAL + 255) / 256)

__global__ void __launch_bounds__(256) buildprep_kernel(
    const float* __restrict__ adj,
    const float* __restrict__ W_out, const float* __restrict__ W_in,
    const float* __restrict__ Wx,    const float* __restrict__ Wh,
    const float* __restrict__ b_out, const float* __restrict__ b_in)
{
    const int bx = blockIdx.x;
    if (bx < BUILD_BLOCKS) {
        long i = (long)bx * 256 + threadIdx.x;   // float4 index
        const float4 v = reinterpret_cast<const float4*>(adj)[i];
        long base = i << 2;
        float vals[4] = {v.x, v.y, v.z, v.w};
#pragma unroll
        for (int j = 0; j < 4; j++) {
            if (vals[j] != 0.0f) {
                long idx = base + j;
                int c = (int)(idx & 4095);
                int r = (int)((idx >> 12) & 4095);
                int e = (int)(idx >> 24);
                int ro = (e << 12) | r;
                int ci = (e << 12) | c;
                int s = atomicAdd(&g_cnt_raw[ro], 1);
                if (s < MAXW) g_ell_out[ro * MAXW + s] = c;
                int s2 = atomicAdd(&g_cnt_raw[EE*NN + ci], 1);
                if (s2 < MAXW) g_ell_in[ci * MAXW + s2] = r;
            }
        }
    } else {
        int j = (bx - BUILD_BLOCKS) * 256 + threadIdx.x;
        if (j < N_WCAT) { g_Wcat16[j] = __float2half(W_out[j]); return; }
        j -= N_WCAT;
        if (j < N_WCAT) { g_Wcat16[N_WCAT + j] = __float2half(W_in[j]); return; }
        j -= N_WCAT;
        if (j < N_WX)   { g_Wx16[j] = __float2half(Wx[j]); return; }
        j -= N_WX;
        if (j < N_WH)   { g_Wh16[j] = __float2half(Wh[j]); return; }
        j -= N_WH;
        if (j < MSGW)   { g_bcat[j] = (j < EE*HH) ? b_out[j] : b_in[j - EE*HH]; }
    }
}

// Sort ELL rows ascending; clamp counts into g_cnt; re-zero g_cnt_raw.
__global__ void sort_kernel() {
    int gw = blockIdx.x * blockDim.x + threadIdx.x;
    if (gw >= 2 * EE * NN) return;
    int r = (gw < EE * NN) ? gw : gw - EE * NN;
    int* ell = (gw < EE * NN) ? g_ell_out : g_ell_in;
    int raw = g_cnt_raw[gw];
    int c = raw < MAXW ? raw : MAXW;
    g_cnt[gw] = c;
    g_cnt_raw[gw] = 0;
    int* lst = ell + (long)r * MAXW;
    int buf[MAXW];
    for (int i = 0; i < c; i++) buf[i] = lst[i];
    for (int i = 1; i < c; i++) {
        int key = buf[i], k = i - 1;
        while (k >= 0 && buf[k] > key) { buf[k+1] = buf[k]; k--; }
        buf[k+1] = key;
    }
    for (int i = 0; i < c; i++) lst[i] = buf[i];
}

// ----------------------------------------------------------------------------
// fp32 SIMT split-K partial GEMM for init (exact). kChunk % 4 == 0.
// ----------------------------------------------------------------------------
#define BK 8
__global__ void __launch_bounds__(256)
gemm_part(const float* __restrict__ A, int lda,
          const float* __restrict__ W, int ldw,
          int K, int kChunk)
{
    __shared__ float As[BK][128 + 4];
    __shared__ float Ws[BK][128 + 4];
    const int z      = blockIdx.z;
    const int kStart = z * kChunk;
    const int kEnd   = min(kStart + kChunk, K);
    float* C = g_ipart + (long)z * NN * 128;

    const int tx   = threadIdx.x;
    const int row0 = blockIdx.y * 128;
    const int lm   = tx >> 1;
    const int lk4  = (tx & 1) << 2;
    const int tr   = (tx >> 4) << 3;
    const int tc   = (tx & 15) << 3;
    const bool alA = ((lda & 3) == 0);
    const bool alW = ((ldw & 3) == 0);

    float acc[8][8];
#pragma unroll
    for (int i = 0; i < 8; i++)
#pragma unroll
        for (int j = 0; j < 8; j++) acc[i][j] = 0.0f;

    const float* Ap = A + (long)(row0 + lm) * lda + lk4;
    const float* Wp = W + (long)lm * ldw + lk4;

    for (int k0 = kStart; k0 < kEnd; k0 += BK) {
        float a0, a1, a2, a3, w0, w1, w2, w3;
        if (alA && (k0 + lk4 + 3 < kEnd)) {
            float4 t = *reinterpret_cast<const float4*>(Ap + k0);
            a0 = t.x; a1 = t.y; a2 = t.z; a3 = t.w;
        } else {
            a0 = (k0 + lk4 + 0 < kEnd) ? Ap[k0 + 0] : 0.0f;
            a1 = (k0 + lk4 + 1 < kEnd) ? Ap[k0 + 1] : 0.0f;
            a2 = (k0 + lk4 + 2 < kEnd) ? Ap[k0 + 2] : 0.0f;
            a3 = (k0 + lk4 + 3 < kEnd) ? Ap[k0 + 3] : 0.0f;
        }
        if (alW && (k0 + lk4 + 3 < kEnd)) {
            float4 t = *reinterpret_cast<const float4*>(Wp + k0);
            w0 = t.x; w1 = t.y; w2 = t.z; w3 = t.w;
        } else {
            w0 = (k0 + lk4 + 0 < kEnd) ? Wp[k0 + 0] : 0.0f;
            w1 = (k0 + lk4 + 1 < kEnd) ? Wp[k0 + 1] : 0.0f;
            w2 = (k0 + lk4 + 2 < kEnd) ? Wp[k0 + 2] : 0.0f;
            w3 = (k0 + lk4 + 3 < kEnd) ? Wp[k0 + 3] : 0.0f;
        }
        __syncthreads();
        As[lk4 + 0][lm] = a0; As[lk4 + 1][lm] = a1;
        As[lk4 + 2][lm] = a2; As[lk4 + 3][lm] = a3;
        Ws[lk4 + 0][lm] = w0; Ws[lk4 + 1][lm] = w1;
        Ws[lk4 + 2][lm] = w2; Ws[lk4 + 3][lm] = w3;
        __syncthreads();
#pragma unroll
        for (int kk = 0; kk < BK; kk++) {
            float a[8], b[8];
            *reinterpret_cast<float4*>(&a[0]) = *reinterpret_cast<const float4*>(&As[kk][tr]);
            *reinterpret_cast<float4*>(&a[4]) = *reinterpret_cast<const float4*>(&As[kk][tr + 4]);
            *reinterpret_cast<float4*>(&b[0]) = *reinterpret_cast<const float4*>(&Ws[kk][tc]);
            *reinterpret_cast<float4*>(&b[4]) = *reinterpret_cast<const float4*>(&Ws[kk][tc + 4]);
#pragma unroll
            for (int i = 0; i < 8; i++)
#pragma unroll
                for (int j = 0; j < 8; j++)
                    acc[i][j] += a[i] * b[j];
        }
    }
#pragma unroll
    for (int i = 0; i < 8; i++) {
        int row = row0 + tr + i;
#pragma unroll
        for (int j = 0; j < 8; j++)
            C[(long)row * 128 + tc + j] = acc[i][j];
    }
}

// emb = tanh(sum of 4 partials + b_red); build g_init [N,144]
__global__ void concat_kernel(const float* __restrict__ states,
                              const float* __restrict__ sp,
                              const float* __restrict__ b_red) {
    int i = blockIdx.x * blockDim.x + threadIdx.x;
    if (i >= NN * 144) return;
    int n = i / 144, j = i % 144;
    float v;
    if (j < 128) {
        long o = (long)n * 128 + j;
        float s = b_red[j];
#pragma unroll
        for (int z = 0; z < 4; z++) s += g_ipart[(long)z * NN * 128 + o];
        v = tanhf(s);
    }
    else if (j < 138) v = states[n * 10 + (j - 128)];
    else              v = sp[n * 6 + (j - 138)];
    g_init[i] = v;
}

// h0 = tanh(sum of 2 partials + b_init); writes fp32 h and fp16 h16
__global__ void h0_kernel(const float* __restrict__ b_init, float* __restrict__ h) {
    int i = blockIdx.x * blockDim.x + threadIdx.x;
    if (i >= NN * 128) return;
    int j = i & 127;
    float v = tanhf(b_init[j] + g_ipart[i] + g_ipart[(long)NN * 128 + i]);
    h[i] = v;
    g_h16[i] = __float2half(v);
}

// ----------------------------------------------------------------------------
// HMMA GEMM with cp.async double-buffered mainloop.
// ----------------------------------------------------------------------------
__device__ __forceinline__ void ldsm4(uint32_t* r, uint32_t addr) {
    asm volatile("ldmatrix.sync.aligned.m8n8.x4.shared.b16 {%0,%1,%2,%3}, [%4];\n"
        : "=r"(r[0]), "=r"(r[1]), "=r"(r[2]), "=r"(r[3]) : "r"(addr));
}
__device__ __forceinline__ void mma16816(float* c, const uint32_t* a, const uint32_t* b) {
    asm volatile("mma.sync.aligned.m16n8k16.row.col.f32.f16.f16.f32 "
        "{%0,%1,%2,%3}, {%4,%5,%6,%7}, {%8,%9}, {%0,%1,%2,%3};\n"
        : "+f"(c[0]), "+f"(c[1]), "+f"(c[2]), "+f"(c[3])
        : "r"(a[0]), "r"(a[1]), "r"(a[2]), "r"(a[3]), "r"(b[0]), "r"(b[1]));
}

#define SLD 40                 // smem row stride in halves
#define STG_H (128 * SLD)      // halves per stage buffer

__device__ __forceinline__ void hgemm_main(
    __half* smem,
    const __half* __restrict__ A, int lda,
    const __half* __restrict__ Bm, int ldb,
    int K, int row0, int col0, float acc[4][4][4])
{
    const int tid  = threadIdx.x;
    const int lane = tid & 31;
    const int warp = tid >> 5;
    const int wr   = warp >> 2;
    const int wc   = warp & 3;

    __half* sA = smem;
    __half* sB = smem + 2 * STG_H;

    const uint32_t aBase = (uint32_t)__cvta_generic_to_shared(sA);
    const uint32_t bBase = (uint32_t)__cvta_generic_to_shared(sB);

    const int aRow  = (lane & 15);
    const int aKoff = (lane >> 4) << 3;
    const int bRow  = (lane & 7) | ((lane & 16) >> 1);
    const int bKoff = (lane & 8);

    const int r_  = tid >> 2;     // 0..63
    const int kc_ = tid & 3;

    auto load_stage = [&](int st, int k0) {
#pragma unroll
        for (int i = 0; i < 2; i++) {
            int r = r_ + (i << 6);
            __pipeline_memcpy_async(&sA[st * STG_H + r * SLD + kc_ * 8],
                                    &A[(long)(row0 + r) * lda + k0 + kc_ * 8], 16);
            __pipeline_memcpy_async(&sB[st * STG_H + r * SLD + kc_ * 8],
                                    &Bm[(long)(col0 + r) * ldb + k0 + kc_ * 8], 16);
        }
        __pipeline_commit();
    };

    const int KT = K >> 5;
    load_stage(0, 0);

    for (int kt = 0; kt < KT; kt++) {
        __pipeline_wait_prior(0);
        __syncthreads();
        if (kt + 1 < KT) load_stage((kt + 1) & 1, (kt + 1) << 5);
        const int st = kt & 1;
#pragma unroll
        for (int kk = 0; kk < 2; kk++) {
            uint32_t a[4][4], b[4][2];
#pragma unroll
            for (int mt = 0; mt < 4; mt++) {
                uint32_t addr = aBase + (uint32_t)((st * STG_H +
                    (wr * 64 + mt * 16 + aRow) * SLD + kk * 16 + aKoff) * 2);
                ldsm4(a[mt], addr);
            }
#pragma unroll
            for (int j = 0; j < 2; j++) {
                uint32_t r4[4];
                uint32_t addr = bBase + (uint32_t)((st * STG_H +
                    (wc * 32 + j * 16 + bRow) * SLD + kk * 16 + bKoff) * 2);
                ldsm4(r4, addr);
                b[2 * j][0]     = r4[0]; b[2 * j][1]     = r4[1];
                b[2 * j + 1][0] = r4[2]; b[2 * j + 1][1] = r4[3];
            }
#pragma unroll
            for (int mt = 0; mt < 4; mt++)
#pragma unroll
                for (int nt = 0; nt < 4; nt++)
                    mma16816(acc[mt][nt], a[mt], b[nt]);
        }
        __syncthreads();
    }
}

template<int ACT, typename OutT>
__global__ void __launch_bounds__(256)
hgemm(const __half* __restrict__ A, int lda,
      const __half* __restrict__ Bm, int ldb,
      const float* __restrict__ bias,
      OutT* __restrict__ C, int ldc, int K)
{
    __shared__ __half smem[4 * STG_H];
    const int lane = threadIdx.x & 31;
    const int warp = threadIdx.x >> 5;
    const int wr   = warp >> 2;
    const int wc   = warp & 3;
    const int row0 = blockIdx.y * 128;
    const int col0 = blockIdx.x * 128;

    float acc[4][4][4];
#pragma unroll
    for (int i = 0; i < 4; i++)
#pragma unroll
        for (int j = 0; j < 4; j++)
#pragma unroll
            for (int q = 0; q < 4; q++) acc[i][j][q] = 0.0f;

    hgemm_main(smem, A, lda, Bm, ldb, K, row0, col0, acc);

    const int g   = lane >> 2;
    const int tc2 = (lane & 3) << 1;
#pragma unroll
    for (int mt = 0; mt < 4; mt++) {
        int r0 = row0 + wr * 64 + mt * 16 + g;
#pragma unroll
        for (int nt = 0; nt < 4; nt++) {
            int col = col0 + wc * 32 + nt * 8 + tc2;
            float b0 = 0.f, b1 = 0.f;
            if (bias) { b0 = bias[col]; b1 = bias[col + 1]; }
            float v00 = acc[mt][nt][0] + b0, v01 = acc[mt][nt][1] + b1;
            float v10 = acc[mt][nt][2] + b0, v11 = acc[mt][nt][3] + b1;
            if (ACT == 1) { v00 = tanhf(v00); v01 = tanhf(v01);
                            v10 = tanhf(v10); v11 = tanhf(v11); }
            if constexpr (sizeof(OutT) == 2) {
                __half2 p0 = __floats2half2_rn(v00, v01);
                __half2 p1 = __floats2half2_rn(v10, v11);
                *reinterpret_cast<__half2*>(&C[(long)r0 * ldc + col])       = p0;
                *reinterpret_cast<__half2*>(&C[(long)(r0 + 8) * ldc + col]) = p1;
            } else {
                *reinterpret_cast<float2*>(&C[(long)r0 * ldc + col])       = make_float2(v00, v01);
                *reinterpret_cast<float2*>(&C[(long)(r0 + 8) * ldc + col]) = make_float2(v10, v11);
            }
        }
    }
}

// Fused gx(split-K=4) + gh launch. z 0..3: gx partial z (K=512); z==4: gh.
__global__ void __launch_bounds__(256) gxgh_kernel(const float* __restrict__ bh) {
    __shared__ __half smem[4 * STG_H];

    const int z = blockIdx.z;
    const __half* A;  const __half* Bm;
    const float* bias; float* C;
    int lda, ldb, K;
    if (z < 4) {
        A = g_msg16 + z * 512;  lda = MSGW;
        Bm = g_Wx16 + z * 512;  ldb = MSGW;
        C = g_gx + (long)z * NN * G3;
        bias = nullptr; K = 512;
    } else {
        A = g_h16;   lda = HH;
        Bm = g_Wh16; ldb = HH;
        C = g_gh;
        bias = bh; K = 128;
    }
    const int ldc = G3;
    const int lane = threadIdx.x & 31;
    const int warp = threadIdx.x >> 5;
    const int wr   = warp >> 2;
    const int wc   = warp & 3;
    const int row0 = blockIdx.y * 128;
    const int col0 = blockIdx.x * 128;

    float acc[4][4][4];
#pragma unroll
    for (int i = 0; i < 4; i++)
#pragma unroll
        for (int j = 0; j < 4; j++)
#pragma unroll
            for (int q = 0; q < 4; q++) acc[i][j][q] = 0.0f;

    hgemm_main(smem, A, lda, Bm, ldb, K, row0, col0, acc);

    const int g   = lane >> 2;
    const int tc2 = (lane & 3) << 1;
#pragma unroll
    for (int mt = 0; mt < 4; mt++) {
        int r0 = row0 + wr * 64 + mt * 16 + g;
#pragma unroll
        for (int nt = 0; nt < 4; nt++) {
            int col = col0 + wc * 32 + nt * 8 + tc2;
            float b0 = 0.f, b1 = 0.f;
            if (bias) { b0 = bias[col]; b1 = bias[col + 1]; }
            *reinterpret_cast<float2*>(&C[(long)r0 * ldc + col]) =
                make_float2(acc[mt][nt][0] + b0, acc[mt][nt][1] + b1);
            *reinterpret_cast<float2*>(&C[(long)(r0 + 8) * ldc + col]) =
                make_float2(acc[mt][nt][2] + b0, acc[mt][nt][3] + b1);
        }
    }
}

// ----------------------------------------------------------------------------
// SpMM (R11-proven): one warp per (dir,e,n) row; unroll 4.
// ----------------------------------------------------------------------------
__global__ void spmm_kernel() {
    int gw   = (blockIdx.x << 3) + (threadIdx.x >> 5);
    int lane = threadIdx.x & 31;
    int dir  = gw >> 15;
    int en   = gw & 32767;
    const int* ell = dir ? g_ell_in : g_ell_out;

    int c = g_cnt[dir * EE * NN + en];
    const int* lst = ell + (long)en * MAXW;
    int e = en >> 12;
    int n = en & 4095;
    int base = (dir << 10) + (e << 7);
    int fl   = (lane & 15) << 3;
    int s0   = lane >> 4;

    float acc[8];
#pragma unroll
    for (int j = 0; j < 8; j++) acc[j] = 0.f;

#pragma unroll 4
    for (int s = s0; s < c; s += 2) {
        int col = lst[s];
        int4 u = *reinterpret_cast<const int4*>(&g_hs16[(long)col * MSGW + base + fl]);
        const __half2* hp = reinterpret_cast<const __half2*>(&u);
#pragma unroll
        for (int j = 0; j < 4; j++) {
            float2 f = __half22float2(hp[j]);
            acc[2 * j]     += f.x;
            acc[2 * j + 1] += f.y;
        }
    }
#pragma unroll
    for (int j = 0; j < 8; j++)
        acc[j] += __shfl_down_sync(0xffffffffu, acc[j], 16);

    if (lane < 16) {
        __half2 o[4];
#pragma unroll
        for (int j = 0; j < 4; j++) o[j] = __floats2half2_rn(acc[2 * j], acc[2 * j + 1]);
        *reinterpret_cast<int4*>(&g_msg16[(long)n * MSGW + base + fl]) =
            *reinterpret_cast<const int4*>(o);
    }
}

// ----------------------------------------------------------------------------
// LayerNorm-GRU update. One block (128 threads) per node. Sums 4 gx partials.
// ----------------------------------------------------------------------------
__device__ __forceinline__ void stats128(float x, float* red, float& mean, float& var) {
    float s = x, q = x * x;
#pragma unroll
    for (int o = 16; o > 0; o >>= 1) {
        s += __shfl_xor_sync(0xffffffffu, s, o);
        q += __shfl_xor_sync(0xffffffffu, q, o);
    }
    int w = threadIdx.x >> 5;
    __syncthreads();
    if ((threadIdx.x & 31) == 0) { red[w] = s; red[4 + w] = q; }
    __syncthreads();
    s = red[0] + red[1] + red[2] + red[3];
    q = red[4] + red[5] + red[6] + red[7];
    mean = s * (1.0f / 128.0f);
    var  = q * (1.0f / 128.0f) - mean * mean;
}

__global__ void gru_kernel(const float* __restrict__ bx,
                           const float* __restrict__ gamma,
                           const float* __restrict__ beta,
                           float* __restrict__ h) {
    __shared__ float red[8];
    int n = blockIdx.x, j = threadIdx.x;
    const long rb = (long)n * G3;
    const long stride = (long)NN * G3;
    const float* ghr = g_gh + rb;

    float xr = bx[j], xz = bx[128 + j], xn = bx[256 + j];
#pragma unroll
    for (int z = 0; z < 4; z++) {
        const float* gxz = g_gx + (long)z * stride + rb;
        xr += gxz[j];
        xz += gxz[128 + j];
        xn += gxz[256 + j];
    }
    float hr = ghr[j], hz = ghr[128 + j], hn = ghr[256 + j];
    float hv = h[(long)n * 128 + j];

    float m, v;
    float ar = xr + hr;
    stats128(ar, red, m, v);
    float r = 1.0f / (1.0f + expf(-((ar - m) * rsqrtf(v + 1e-5f) * gamma[j] + beta[j])));

    float az = xz + hz;
    stats128(az, red, m, v);
    float z = 1.0f / (1.0f + expf(-((az - m) * rsqrtf(v + 1e-5f) * gamma[128 + j] + beta[128 + j])));

    float an = xn + r * hn;
    stats128(an, red, m, v);
    float nn = tanhf((an - m) * rsqrtf(v + 1e-5f) * gamma[256 + j] + beta[256 + j]);

    float hnew = (1.0f - z) * nn + z * hv;
    h[(long)n * 128 + j] = hnew;
    g_h16[(long)n * 128 + j] = __float2half(hnew);
}

// ----------------------------------------------------------------------------
// Host orchestration — two-stream fork/join to overlap the independent
// prologue chains:  side: buildprep -> sort   |   main: init GEMM chain + hs0
// Stream/events created once on the first (uncaptured) call; capture uses the
// standard event fork-join pattern.
// ----------------------------------------------------------------------------
extern "C" void kernel_launch(void* const* d_in, const int* in_sizes, int n_in,
                              void* d_out, int out_size) {
    (void)in_sizes; (void)n_in; (void)out_size;
    const float* adj    = (const float*)d_in[0];
    const float* states = (const float*)d_in[1];
    const float* vecs   = (const float*)d_in[3];
    const float* sp     = (const float*)d_in[4];
    const float* W_red  = (const float*)d_in[5];
    const float* b_red  = (const float*)d_in[6];
    const float* W_init = (const float*)d_in[7];
    const float* b_init = (const float*)d_in[8];
    const float* W_out  = (const float*)d_in[9];
    const float* b_out  = (const float*)d_in[10];
    const float* W_in   = (const float*)d_in[11];
    const float* b_in   = (const float*)d_in[12];
    const float* Wx     = (const float*)d_in[13];
    const float* bx     = (const float*)d_in[14];
    const float* Wh     = (const float*)d_in[15];
    const float* bh     = (const float*)d_in[16];
    const float* gamma  = (const float*)d_in[17];
    const float* beta   = (const float*)d_in[18];
    float* h = (float*)d_out;

    float *p_init, *p_bcat;
    __half *p_hs, *p_h16, *p_Wcat;
    cudaGetSymbolAddress((void**)&p_init, g_init);
    cudaGetSymbolAddress((void**)&p_bcat, g_bcat);
    cudaGetSymbolAddress((void**)&p_hs,   g_hs16);
    cudaGetSymbolAddress((void**)&p_h16,  g_h16);
    cudaGetSymbolAddress((void**)&p_Wcat, g_Wcat16);

    static cudaStream_t sSide = nullptr;
    static cudaEvent_t  evFork = nullptr, evJoin = nullptr;
    if (sSide == nullptr) {
        cudaStreamCreateWithFlags(&sSide, cudaStreamNonBlocking);
        cudaEventCreateWithFlags(&evFork, cudaEventDisableTiming);
        cudaEventCreateWithFlags(&evJoin, cudaEventDisableTiming);
    }

    // fork: side stream runs build+sort concurrently with the init chain
    cudaEventRecord(evFork, 0);
    cudaStreamWaitEvent(sSide, evFork, 0);

    buildprep_kernel<<<BUILD_BLOCKS + PREP_BLOCKS, 256, 0, sSide>>>(
        adj, W_out, W_in, Wx, Wh, b_out, b_in);
    sort_kernel<<<2 * EE * NN / 256, 256, 0, sSide>>>();
    cudaEventRecord(evJoin, sSide);

    // main stream: init chain (independent of build/sort)
    gemm_part<<<dim3(1, 32, 4), 256>>>(vecs, 300, W_red, 300, 300, 76);
    concat_kernel<<<(NN * 144 + 255) / 256, 256>>>(states, sp, b_red);
    gemm_part<<<dim3(1, 32, 2), 256>>>(p_init, 144, W_init, 144, 144, 72);
    h0_kernel<<<(NN * 128 + 255) / 256, 256>>>(b_init, h);
    // step-0 hs depends only on h16 + Wcat; Wcat comes from buildprep's prep
    // role which is on the side stream -> must join BEFORE hs.  Join here.
    cudaStreamWaitEvent(0, evJoin, 0);

    // ---- T message-passing + GRU steps (all on main stream) ----
    for (int t = 0; t < TSTEPS; t++) {
        hgemm<1, __half><<<dim3(16, 32), 256>>>(p_h16, HH, p_Wcat, HH, p_bcat,
                                                p_hs, MSGW, HH);
        spmm_kernel<<<8192, 256>>>();
        gxgh_kernel<<<dim3(3, 32, 5), 256>>>(bh);
        gru_kernel<<<NN, 128>>>(bx, gamma, beta, h);
    }
}

// round 14
// speedup vs baseline: 1.1591x; 1.1591x over previous
#include <cuda_runtime.h>
#include <cuda_fp16.h>
#include <cuda_pipeline.h>
#include <cstdint>

#define NN   4096
#define EE   8
#define HH   128
#define MAXW 96
#define MSGW (2*EE*HH)   /* 2048 */
#define G3   384
#define TSTEPS 4

// ----------------------------------------------------------------------------
// Device-global scratch (allocation-free contract; zero-initialized at load)
// ----------------------------------------------------------------------------
__device__ int    g_cnt_raw[2*EE*NN];    // build target; re-zeroed by sort
__device__ int    g_cnt    [2*EE*NN];    // clamped counts for spmm
__device__ int    g_ell_out[EE*NN*MAXW];
__device__ int    g_ell_in [EE*NN*MAXW];
__device__ __half g_hs16  [NN*MSGW];     // [n][dir*1024 + e*128 + h]
__device__ __half g_msg16 [NN*MSGW];
__device__ __half g_h16   [NN*HH];
__device__ __half g_Wcat16[MSGW*HH];
__device__ __half g_Wx16  [G3*MSGW];
__device__ __half g_Wh16  [G3*HH];
__device__ float  g_bcat  [MSGW];
__device__ float  g_gx    [NN*G3];       // single full-K gx buffer
__device__ float  g_gh    [NN*G3];
__device__ float  g_ipart [4*NN*128];    // init GEMM split-K partials
__device__ float  g_init  [NN*144];

// ----------------------------------------------------------------------------
// Fused build + weight-prep (both low-register memory-bound roles).
// ----------------------------------------------------------------------------
#define N_WCAT (EE*HH*HH)
#define N_WX   (G3*MSGW)
#define N_WH   (G3*HH)
#define PREP_TOTAL (2*N_WCAT + N_WX + N_WH + MSGW)
#define BUILD_BLOCKS (EE * NN * (NN / 4) / 256)       /* 131072 */
#define PREP_BLOCKS  ((PREP_TOTAL + 255) / 256)

__global__ void __launch_bounds__(256) buildprep_kernel(
    const float* __restrict__ adj,
    const float* __restrict__ W_out, const float* __restrict__ W_in,
    const float* __restrict__ Wx,    const float* __restrict__ Wh,
    const float* __restrict__ b_out, const float* __restrict__ b_in)
{
    const int bx = blockIdx.x;
    if (bx < BUILD_BLOCKS) {
        long i = (long)bx * 256 + threadIdx.x;   // float4 index
        const float4 v = reinterpret_cast<const float4*>(adj)[i];
        long base = i << 2;
        float vals[4] = {v.x, v.y, v.z, v.w};
#pragma unroll
        for (int j = 0; j < 4; j++) {
            if (vals[j] != 0.0f) {
                long idx = base + j;
                int c = (int)(idx & 4095);
                int r = (int)((idx >> 12) & 4095);
                int e = (int)(idx >> 24);
                int ro = (e << 12) | r;
                int ci = (e << 12) | c;
                int s = atomicAdd(&g_cnt_raw[ro], 1);
                if (s < MAXW) g_ell_out[ro * MAXW + s] = c;
                int s2 = atomicAdd(&g_cnt_raw[EE*NN + ci], 1);
                if (s2 < MAXW) g_ell_in[ci * MAXW + s2] = r;
            }
        }
    } else {
        int j = (bx - BUILD_BLOCKS) * 256 + threadIdx.x;
        if (j < N_WCAT) { g_Wcat16[j] = __float2half(W_out[j]); return; }
        j -= N_WCAT;
        if (j < N_WCAT) { g_Wcat16[N_WCAT + j] = __float2half(W_in[j]); return; }
        j -= N_WCAT;
        if (j < N_WX)   { g_Wx16[j] = __float2half(Wx[j]); return; }
        j -= N_WX;
        if (j < N_WH)   { g_Wh16[j] = __float2half(Wh[j]); return; }
        j -= N_WH;
        if (j < MSGW)   { g_bcat[j] = (j < EE*HH) ? b_out[j] : b_in[j - EE*HH]; }
    }
}

// Sort ELL rows ascending; clamp counts into g_cnt; re-zero g_cnt_raw.
__global__ void sort_kernel() {
    int gw = blockIdx.x * blockDim.x + threadIdx.x;
    if (gw >= 2 * EE * NN) return;
    int r = (gw < EE * NN) ? gw : gw - EE * NN;
    int* ell = (gw < EE * NN) ? g_ell_out : g_ell_in;
    int raw = g_cnt_raw[gw];
    int c = raw < MAXW ? raw : MAXW;
    g_cnt[gw] = c;
    g_cnt_raw[gw] = 0;
    int* lst = ell + (long)r * MAXW;
    int buf[MAXW];
    for (int i = 0; i < c; i++) buf[i] = lst[i];
    for (int i = 1; i < c; i++) {
        int key = buf[i], k = i - 1;
        while (k >= 0 && buf[k] > key) { buf[k+1] = buf[k]; k--; }
        buf[k+1] = key;
    }
    for (int i = 0; i < c; i++) lst[i] = buf[i];
}

// ----------------------------------------------------------------------------
// fp32 SIMT split-K partial GEMM for init (exact). kChunk % 4 == 0.
// ----------------------------------------------------------------------------
#define BK 8
__global__ void __launch_bounds__(256)
gemm_part(const float* __restrict__ A, int lda,
          const float* __restrict__ W, int ldw,
          int K, int kChunk)
{
    __shared__ float As[BK][128 + 4];
    __shared__ float Ws[BK][128 + 4];
    const int z      = blockIdx.z;
    const int kStart = z * kChunk;
    const int kEnd   = min(kStart + kChunk, K);
    float* C = g_ipart + (long)z * NN * 128;

    const int tx   = threadIdx.x;
    const int row0 = blockIdx.y * 128;
    const int lm   = tx >> 1;
    const int lk4  = (tx & 1) << 2;
    const int tr   = (tx >> 4) << 3;
    const int tc   = (tx & 15) << 3;
    const bool alA = ((lda & 3) == 0);
    const bool alW = ((ldw & 3) == 0);

    float acc[8][8];
#pragma unroll
    for (int i = 0; i < 8; i++)
#pragma unroll
        for (int j = 0; j < 8; j++) acc[i][j] = 0.0f;

    const float* Ap = A + (long)(row0 + lm) * lda + lk4;
    const float* Wp = W + (long)lm * ldw + lk4;

    for (int k0 = kStart; k0 < kEnd; k0 += BK) {
        float a0, a1, a2, a3, w0, w1, w2, w3;
        if (alA && (k0 + lk4 + 3 < kEnd)) {
            float4 t = *reinterpret_cast<const float4*>(Ap + k0);
            a0 = t.x; a1 = t.y; a2 = t.z; a3 = t.w;
        } else {
            a0 = (k0 + lk4 + 0 < kEnd) ? Ap[k0 + 0] : 0.0f;
            a1 = (k0 + lk4 + 1 < kEnd) ? Ap[k0 + 1] : 0.0f;
            a2 = (k0 + lk4 + 2 < kEnd) ? Ap[k0 + 2] : 0.0f;
            a3 = (k0 + lk4 + 3 < kEnd) ? Ap[k0 + 3] : 0.0f;
        }
        if (alW && (k0 + lk4 + 3 < kEnd)) {
            float4 t = *reinterpret_cast<const float4*>(Wp + k0);
            w0 = t.x; w1 = t.y; w2 = t.z; w3 = t.w;
        } else {
            w0 = (k0 + lk4 + 0 < kEnd) ? Wp[k0 + 0] : 0.0f;
            w1 = (k0 + lk4 + 1 < kEnd) ? Wp[k0 + 1] : 0.0f;
            w2 = (k0 + lk4 + 2 < kEnd) ? Wp[k0 + 2] : 0.0f;
            w3 = (k0 + lk4 + 3 < kEnd) ? Wp[k0 + 3] : 0.0f;
        }
        __syncthreads();
        As[lk4 + 0][lm] = a0; As[lk4 + 1][lm] = a1;
        As[lk4 + 2][lm] = a2; As[lk4 + 3][lm] = a3;
        Ws[lk4 + 0][lm] = w0; Ws[lk4 + 1][lm] = w1;
        Ws[lk4 + 2][lm] = w2; Ws[lk4 + 3][lm] = w3;
        __syncthreads();
#pragma unroll
        for (int kk = 0; kk < BK; kk++) {
            float a[8], b[8];
            *reinterpret_cast<float4*>(&a[0]) = *reinterpret_cast<const float4*>(&As[kk][tr]);
            *reinterpret_cast<float4*>(&a[4]) = *reinterpret_cast<const float4*>(&As[kk][tr + 4]);
            *reinterpret_cast<float4*>(&b[0]) = *reinterpret_cast<const float4*>(&Ws[kk][tc]);
            *reinterpret_cast<float4*>(&b[4]) = *reinterpret_cast<const float4*>(&Ws[kk][tc + 4]);
#pragma unroll
            for (int i = 0; i < 8; i++)
#pragma unroll
                for (int j = 0; j < 8; j++)
                    acc[i][j] += a[i] * b[j];
        }
    }
#pragma unroll
    for (int i = 0; i < 8; i++) {
        int row = row0 + tr + i;
#pragma unroll
        for (int j = 0; j < 8; j++)
            C[(long)row * 128 + tc + j] = acc[i][j];
    }
}

// emb = tanh(sum of 4 partials + b_red); build g_init [N,144]
__global__ void concat_kernel(const float* __restrict__ states,
                              const float* __restrict__ sp,
                              const float* __restrict__ b_red) {
    int i = blockIdx.x * blockDim.x + threadIdx.x;
    if (i >= NN * 144) return;
    int n = i / 144, j = i % 144;
    float v;
    if (j < 128) {
        long o = (long)n * 128 + j;
        float s = b_red[j];
#pragma unroll
        for (int z = 0; z < 4; z++) s += g_ipart[(long)z * NN * 128 + o];
        v = tanhf(s);
    }
    else if (j < 138) v = states[n * 10 + (j - 128)];
    else              v = sp[n * 6 + (j - 138)];
    g_init[i] = v;
}

// h0 = tanh(sum of 2 partials + b_init); writes fp32 h and fp16 h16
__global__ void h0_kernel(const float* __restrict__ b_init, float* __restrict__ h) {
    int i = blockIdx.x * blockDim.x + threadIdx.x;
    if (i >= NN * 128) return;
    int j = i & 127;
    float v = tanhf(b_init[j] + g_ipart[i] + g_ipart[(long)NN * 128 + i]);
    h[i] = v;
    g_h16[i] = __float2half(v);
}

// ----------------------------------------------------------------------------
// HMMA GEMM with cp.async double-buffered mainloop.
// ----------------------------------------------------------------------------
__device__ __forceinline__ void ldsm4(uint32_t* r, uint32_t addr) {
    asm volatile("ldmatrix.sync.aligned.m8n8.x4.shared.b16 {%0,%1,%2,%3}, [%4];\n"
        : "=r"(r[0]), "=r"(r[1]), "=r"(r[2]), "=r"(r[3]) : "r"(addr));
}
__device__ __forceinline__ void mma16816(float* c, const uint32_t* a, const uint32_t* b) {
    asm volatile("mma.sync.aligned.m16n8k16.row.col.f32.f16.f16.f32 "
        "{%0,%1,%2,%3}, {%4,%5,%6,%7}, {%8,%9}, {%0,%1,%2,%3};\n"
        : "+f"(c[0]), "+f"(c[1]), "+f"(c[2]), "+f"(c[3])
        : "r"(a[0]), "r"(a[1]), "r"(a[2]), "r"(a[3]), "r"(b[0]), "r"(b[1]));
}

#define SLD 40                 // smem row stride in halves
#define STG_H (128 * SLD)      // halves per stage buffer

__device__ __forceinline__ void hgemm_main(
    __half* smem,
    const __half* __restrict__ A, int lda,
    const __half* __restrict__ Bm, int ldb,
    int K, int row0, int col0, float acc[4][4][4])
{
    const int tid  = threadIdx.x;
    const int lane = tid & 31;
    const int warp = tid >> 5;
    const int wr   = warp >> 2;
    const int wc   = warp & 3;

    __half* sA = smem;
    __half* sB = smem + 2 * STG_H;

    const uint32_t aBase = (uint32_t)__cvta_generic_to_shared(sA);
    const uint32_t bBase = (uint32_t)__cvta_generic_to_shared(sB);

    const int aRow  = (lane & 15);
    const int aKoff = (lane >> 4) << 3;
    const int bRow  = (lane & 7) | ((lane & 16) >> 1);
    const int bKoff = (lane & 8);

    const int r_  = tid >> 2;     // 0..63
    const int kc_ = tid & 3;

    auto load_stage = [&](int st, int k0) {
#pragma unroll
        for (int i = 0; i < 2; i++) {
            int r = r_ + (i << 6);
            __pipeline_memcpy_async(&sA[st * STG_H + r * SLD + kc_ * 8],
                                    &A[(long)(row0 + r) * lda + k0 + kc_ * 8], 16);
            __pipeline_memcpy_async(&sB[st * STG_H + r * SLD + kc_ * 8],
                                    &Bm[(long)(col0 + r) * ldb + k0 + kc_ * 8], 16);
        }
        __pipeline_commit();
    };

    const int KT = K >> 5;
    load_stage(0, 0);

    for (int kt = 0; kt < KT; kt++) {
        __pipeline_wait_prior(0);
        __syncthreads();
        if (kt + 1 < KT) load_stage((kt + 1) & 1, (kt + 1) << 5);
        const int st = kt & 1;
#pragma unroll
        for (int kk = 0; kk < 2; kk++) {
            uint32_t a[4][4], b[4][2];
#pragma unroll
            for (int mt = 0; mt < 4; mt++) {
                uint32_t addr = aBase + (uint32_t)((st * STG_H +
                    (wr * 64 + mt * 16 + aRow) * SLD + kk * 16 + aKoff) * 2);
                ldsm4(a[mt], addr);
            }
#pragma unroll
            for (int j = 0; j < 2; j++) {
                uint32_t r4[4];
                uint32_t addr = bBase + (uint32_t)((st * STG_H +
                    (wc * 32 + j * 16 + bRow) * SLD + kk * 16 + bKoff) * 2);
                ldsm4(r4, addr);
                b[2 * j][0]     = r4[0]; b[2 * j][1]     = r4[1];
                b[2 * j + 1][0] = r4[2]; b[2 * j + 1][1] = r4[3];
            }
#pragma unroll
            for (int mt = 0; mt < 4; mt++)
#pragma unroll
                for (int nt = 0; nt < 4; nt++)
                    mma16816(acc[mt][nt], a[mt], b[nt]);
        }
        __syncthreads();
    }
}

template<int ACT, typename OutT>
__global__ void __launch_bounds__(256)
hgemm(const __half* __restrict__ A, int lda,
      const __half* __restrict__ Bm, int ldb,
      const float* __restrict__ bias,
      OutT* __restrict__ C, int ldc, int K)
{
    __shared__ __half smem[4 * STG_H];
    const int lane = threadIdx.x & 31;
    const int warp = threadIdx.x >> 5;
    const int wr   = warp >> 2;
    const int wc   = warp & 3;
    const int row0 = blockIdx.y * 128;
    const int col0 = blockIdx.x * 128;

    float acc[4][4][4];
#pragma unroll
    for (int i = 0; i < 4; i++)
#pragma unroll
        for (int j = 0; j < 4; j++)
#pragma unroll
            for (int q = 0; q < 4; q++) acc[i][j][q] = 0.0f;

    hgemm_main(smem, A, lda, Bm, ldb, K, row0, col0, acc);

    const int g   = lane >> 2;
    const int tc2 = (lane & 3) << 1;
#pragma unroll
    for (int mt = 0; mt < 4; mt++) {
        int r0 = row0 + wr * 64 + mt * 16 + g;
#pragma unroll
        for (int nt = 0; nt < 4; nt++) {
            int col = col0 + wc * 32 + nt * 8 + tc2;
            float b0 = 0.f, b1 = 0.f;
            if (bias) { b0 = bias[col]; b1 = bias[col + 1]; }
            float v00 = acc[mt][nt][0] + b0, v01 = acc[mt][nt][1] + b1;
            float v10 = acc[mt][nt][2] + b0, v11 = acc[mt][nt][3] + b1;
            if (ACT == 1) { v00 = tanhf(v00); v01 = tanhf(v01);
                            v10 = tanhf(v10); v11 = tanhf(v11); }
            if constexpr (sizeof(OutT) == 2) {
                __half2 p0 = __floats2half2_rn(v00, v01);
                __half2 p1 = __floats2half2_rn(v10, v11);
                *reinterpret_cast<__half2*>(&C[(long)r0 * ldc + col])       = p0;
                *reinterpret_cast<__half2*>(&C[(long)(r0 + 8) * ldc + col]) = p1;
            } else {
                *reinterpret_cast<float2*>(&C[(long)r0 * ldc + col])       = make_float2(v00, v01);
                *reinterpret_cast<float2*>(&C[(long)(r0 + 8) * ldc + col]) = make_float2(v10, v11);
            }
        }
    }
}

// Fused gx(full K=2048) + gh launch. z==0: gx; z==1: gh (K=128, bias).
__global__ void __launch_bounds__(256) gxgh_kernel(const float* __restrict__ bh) {
    __shared__ __half smem[4 * STG_H];

    const int z = blockIdx.z;
    const __half* A;  const __half* Bm;
    const float* bias; float* C;
    int lda, ldb, K;
    if (z == 0) {
        A = g_msg16;  lda = MSGW;
        Bm = g_Wx16;  ldb = MSGW;
        C = g_gx;
        bias = nullptr; K = MSGW;
    } else {
        A = g_h16;   lda = HH;
        Bm = g_Wh16; ldb = HH;
        C = g_gh;
        bias = bh; K = 128;
    }
    const int ldc = G3;
    const int lane = threadIdx.x & 31;
    const int warp = threadIdx.x >> 5;
    const int wr   = warp >> 2;
    const int wc   = warp & 3;
    const int row0 = blockIdx.y * 128;
    const int col0 = blockIdx.x * 128;

    float acc[4][4][4];
#pragma unroll
    for (int i = 0; i < 4; i++)
#pragma unroll
        for (int j = 0; j < 4; j++)
#pragma unroll
            for (int q = 0; q < 4; q++) acc[i][j][q] = 0.0f;

    hgemm_main(smem, A, lda, Bm, ldb, K, row0, col0, acc);

    const int g   = lane >> 2;
    const int tc2 = (lane & 3) << 1;
#pragma unroll
    for (int mt = 0; mt < 4; mt++) {
        int r0 = row0 + wr * 64 + mt * 16 + g;
#pragma unroll
        for (int nt = 0; nt < 4; nt++) {
            int col = col0 + wc * 32 + nt * 8 + tc2;
            float b0 = 0.f, b1 = 0.f;
            if (bias) { b0 = bias[col]; b1 = bias[col + 1]; }
            *reinterpret_cast<float2*>(&C[(long)r0 * ldc + col]) =
                make_float2(acc[mt][nt][0] + b0, acc[mt][nt][1] + b1);
            *reinterpret_cast<float2*>(&C[(long)(r0 + 8) * ldc + col]) =
                make_float2(acc[mt][nt][2] + b0, acc[mt][nt][3] + b1);
        }
    }
}

// ----------------------------------------------------------------------------
// SpMM (R11-proven): one warp per (dir,e,n) row; unroll 4.
// ----------------------------------------------------------------------------
__global__ void spmm_kernel() {
    int gw   = (blockIdx.x << 3) + (threadIdx.x >> 5);
    int lane = threadIdx.x & 31;
    int dir  = gw >> 15;
    int en   = gw & 32767;
    const int* ell = dir ? g_ell_in : g_ell_out;

    int c = g_cnt[dir * EE * NN + en];
    const int* lst = ell + (long)en * MAXW;
    int e = en >> 12;
    int n = en & 4095;
    int base = (dir << 10) + (e << 7);
    int fl   = (lane & 15) << 3;
    int s0   = lane >> 4;

    float acc[8];
#pragma unroll
    for (int j = 0; j < 8; j++) acc[j] = 0.f;

#pragma unroll 4
    for (int s = s0; s < c; s += 2) {
        int col = lst[s];
        int4 u = *reinterpret_cast<const int4*>(&g_hs16[(long)col * MSGW + base + fl]);
        const __half2* hp = reinterpret_cast<const __half2*>(&u);
#pragma unroll
        for (int j = 0; j < 4; j++) {
            float2 f = __half22float2(hp[j]);
            acc[2 * j]     += f.x;
            acc[2 * j + 1] += f.y;
        }
    }
#pragma unroll
    for (int j = 0; j < 8; j++)
        acc[j] += __shfl_down_sync(0xffffffffu, acc[j], 16);

    if (lane < 16) {
        __half2 o[4];
#pragma unroll
        for (int j = 0; j < 4; j++) o[j] = __floats2half2_rn(acc[2 * j], acc[2 * j + 1]);
        *reinterpret_cast<int4*>(&g_msg16[(long)n * MSGW + base + fl]) =
            *reinterpret_cast<const int4*>(o);
    }
}

// ----------------------------------------------------------------------------
// LayerNorm-GRU update. One block (128 threads) per node. Single gx buffer.
// ----------------------------------------------------------------------------
__device__ __forceinline__ void stats128(float x, float* red, float& mean, float& var) {
    float s = x, q = x * x;
#pragma unroll
    for (int o = 16; o > 0; o >>= 1) {
        s += __shfl_xor_sync(0xffffffffu, s, o);
        q += __shfl_xor_sync(0xffffffffu, q, o);
    }
    int w = threadIdx.x >> 5;
    __syncthreads();
    if ((threadIdx.x & 31) == 0) { red[w] = s; red[4 + w] = q; }
    __syncthreads();
    s = red[0] + red[1] + red[2] + red[3];
    q = red[4] + red[5] + red[6] + red[7];
    mean = s * (1.0f / 128.0f);
    var  = q * (1.0f / 128.0f) - mean * mean;
}

__global__ void gru_kernel(const float* __restrict__ bx,
                           const float* __restrict__ gamma,
                           const float* __restrict__ beta,
                           float* __restrict__ h) {
    __shared__ float red[8];
    int n = blockIdx.x, j = threadIdx.x;
    const long rb = (long)n * G3;
    const float* gxr = g_gx + rb;
    const float* ghr = g_gh + rb;

    float xr = bx[j]       + gxr[j];
    float xz = bx[128 + j] + gxr[128 + j];
    float xn = bx[256 + j] + gxr[256 + j];
    float hr = ghr[j], hz = ghr[128 + j], hn = ghr[256 + j];
    float hv = h[(long)n * 128 + j];

    float m, v;
    float ar = xr + hr;
    stats128(ar, red, m, v);
    float r = 1.0f / (1.0f + expf(-((ar - m) * rsqrtf(v + 1e-5f) * gamma[j] + beta[j])));

    float az = xz + hz;
    stats128(az, red, m, v);
    float z = 1.0f / (1.0f + expf(-((az - m) * rsqrtf(v + 1e-5f) * gamma[128 + j] + beta[128 + j])));

    float an = xn + r * hn;
    stats128(an, red, m, v);
    float nn = tanhf((an - m) * rsqrtf(v + 1e-5f) * gamma[256 + j] + beta[256 + j]);

    float hnew = (1.0f - z) * nn + z * hv;
    h[(long)n * 128 + j] = hnew;
    g_h16[(long)n * 128 + j] = __float2half(hnew);
}

// ----------------------------------------------------------------------------
// Host orchestration (single stream, R12-proven)
// ----------------------------------------------------------------------------
extern "C" void kernel_launch(void* const* d_in, const int* in_sizes, int n_in,
                              void* d_out, int out_size) {
    (void)in_sizes; (void)n_in; (void)out_size;
    const float* adj    = (const float*)d_in[0];
    const float* states = (const float*)d_in[1];
    const float* vecs   = (const float*)d_in[3];
    const float* sp     = (const float*)d_in[4];
    const float* W_red  = (const float*)d_in[5];
    const float* b_red  = (const float*)d_in[6];
    const float* W_init = (const float*)d_in[7];
    const float* b_init = (const float*)d_in[8];
    const float* W_out  = (const float*)d_in[9];
    const float* b_out  = (const float*)d_in[10];
    const float* W_in   = (const float*)d_in[11];
    const float* b_in   = (const float*)d_in[12];
    const float* Wx     = (const float*)d_in[13];
    const float* bx     = (const float*)d_in[14];
    const float* Wh     = (const float*)d_in[15];
    const float* bh     = (const float*)d_in[16];
    const float* gamma  = (const float*)d_in[17];
    const float* beta   = (const float*)d_in[18];
    float* h = (float*)d_out;

    float *p_init, *p_bcat;
    __half *p_hs, *p_h16, *p_Wcat;
    cudaGetSymbolAddress((void**)&p_init, g_init);
    cudaGetSymbolAddress((void**)&p_bcat, g_bcat);
    cudaGetSymbolAddress((void**)&p_hs,   g_hs16);
    cudaGetSymbolAddress((void**)&p_h16,  g_h16);
    cudaGetSymbolAddress((void**)&p_Wcat, g_Wcat16);

    // 1: fused build scan + weight packing
    buildprep_kernel<<<BUILD_BLOCKS + PREP_BLOCKS, 256>>>(
        adj, W_out, W_in, Wx, Wh, b_out, b_in);

    // 2: emb GEMM partials (split-K=4, aligned chunks)
    gemm_part<<<dim3(1, 32, 4), 256>>>(vecs, 300, W_red, 300, 300, 76);

    // 3: sort ELL rows + clamp counts + re-zero raw
    sort_kernel<<<2 * EE * NN / 256, 256>>>();

    // 4: emb tanh + concat -> g_init
    concat_kernel<<<(NN * 144 + 255) / 256, 256>>>(states, sp, b_red);

    // 5-6: h0 = tanh(init @ W_init^T + b_init)
    gemm_part<<<dim3(1, 32, 2), 256>>>(p_init, 144, W_init, 144, 144, 72);
    h0_kernel<<<(NN * 128 + 255) / 256, 256>>>(b_init, h);

    // ---- T message-passing + GRU steps ----
    for (int t = 0; t < TSTEPS; t++) {
        // hs = tanh(h @ Wcat^T + bcat)  -> fp16 [N,2048]   (pipelined)
        hgemm<1, __half><<<dim3(16, 32), 256>>>(p_h16, HH, p_Wcat, HH, p_bcat,
                                                p_hs, MSGW, HH);
        // sparse aggregation -> msg16 [N,2048]
        spmm_kernel<<<8192, 256>>>();
        // fused: gx (full K=2048) + gh, one launch (pipelined)
        gxgh_kernel<<<dim3(3, 32, 2), 256>>>(bh);
        // LayerNorm-GRU update (gx + bx; writes h fp32 + h16)
        gru_kernel<<<NN, 128>>>(bx, gamma, beta, h);
    }
}

// round 15
// speedup vs baseline: 1.2202x; 1.0527x over previous
#include <cuda_runtime.h>
#include <cuda_fp16.h>
#include <cuda_pipeline.h>
#include <cstdint>

#define NN   4096
#define EE   8
#define HH   128
#define MAXW 96
#define MSGW (2*EE*HH)   /* 2048 */
#define G3   384
#define TSTEPS 4

// ----------------------------------------------------------------------------
// Device-global scratch (allocation-free contract; zero-initialized at load)
// ----------------------------------------------------------------------------
__device__ int    g_cnt_raw[2*EE*NN];    // build target; re-zeroed by sort
__device__ int    g_cnt    [2*EE*NN];    // clamped counts for spmm
__device__ int    g_ell_out[EE*NN*MAXW];
__device__ int    g_ell_in [EE*NN*MAXW];
__device__ __half g_hs16  [NN*MSGW];     // [n][dir*1024 + e*128 + h]
__device__ __half g_msg16 [NN*MSGW];
__device__ __half g_h16   [NN*HH];
__device__ __half g_Wcat16[MSGW*HH];
__device__ __half g_Wx16  [G3*MSGW];
__device__ __half g_Wh16  [G3*HH];
__device__ float  g_bcat  [MSGW];
__device__ float  g_gx    [4*NN*G3];     // split-K=4 partial buffers
__device__ float  g_gh    [NN*G3];
__device__ float  g_ipart [4*NN*128];    // init GEMM split-K partials
__device__ float  g_init  [NN*144];

// ----------------------------------------------------------------------------
// Fused build + weight-prep (both low-register memory-bound roles).
// ----------------------------------------------------------------------------
#define N_WCAT (EE*HH*HH)
#define N_WX   (G3*MSGW)
#define N_WH   (G3*HH)
#define PREP_TOTAL (2*N_WCAT + N_WX + N_WH + MSGW)
#define BUILD_BLOCKS (EE * NN * (NN / 4) / 256)       /* 131072 */
#define PREP_BLOCKS  ((PREP_TOTAL + 255) / 256)

__global__ void __launch_bounds__(256) buildprep_kernel(
    const float* __restrict__ adj,
    const float* __restrict__ W_out, const float* __restrict__ W_in,
    const float* __restrict__ Wx,    const float* __restrict__ Wh,
    const float* __restrict__ b_out, const float* __restrict__ b_in)
{
    const int bx = blockIdx.x;
    if (bx < BUILD_BLOCKS) {
        long i = (long)bx * 256 + threadIdx.x;   // float4 index
        const float4 v = reinterpret_cast<const float4*>(adj)[i];
        long base = i << 2;
        float vals[4] = {v.x, v.y, v.z, v.w};
#pragma unroll
        for (int j = 0; j < 4; j++) {
            if (vals[j] != 0.0f) {
                long idx = base + j;
                int c = (int)(idx & 4095);
                int r = (int)((idx >> 12) & 4095);
                int e = (int)(idx >> 24);
                int ro = (e << 12) | r;
                int ci = (e << 12) | c;
                int s = atomicAdd(&g_cnt_raw[ro], 1);
                if (s < MAXW) g_ell_out[ro * MAXW + s] = c;
                int s2 = atomicAdd(&g_cnt_raw[EE*NN + ci], 1);
                if (s2 < MAXW) g_ell_in[ci * MAXW + s2] = r;
            }
        }
    } else {
        int j = (bx - BUILD_BLOCKS) * 256 + threadIdx.x;
        if (j < N_WCAT) { g_Wcat16[j] = __float2half(W_out[j]); return; }
        j -= N_WCAT;
        if (j < N_WCAT) { g_Wcat16[N_WCAT + j] = __float2half(W_in[j]); return; }
        j -= N_WCAT;
        if (j < N_WX)   { g_Wx16[j] = __float2half(Wx[j]); return; }
        j -= N_WX;
        if (j < N_WH)   { g_Wh16[j] = __float2half(Wh[j]); return; }
        j -= N_WH;
        if (j < MSGW)   { g_bcat[j] = (j < EE*HH) ? b_out[j] : b_in[j - EE*HH]; }
    }
}

// Sort ELL rows ascending; clamp counts into g_cnt; re-zero g_cnt_raw.
__global__ void sort_kernel() {
    int gw = blockIdx.x * blockDim.x + threadIdx.x;
    if (gw >= 2 * EE * NN) return;
    int r = (gw < EE * NN) ? gw : gw - EE * NN;
    int* ell = (gw < EE * NN) ? g_ell_out : g_ell_in;
    int raw = g_cnt_raw[gw];
    int c = raw < MAXW ? raw : MAXW;
    g_cnt[gw] = c;
    g_cnt_raw[gw] = 0;
    int* lst = ell + (long)r * MAXW;
    int buf[MAXW];
    for (int i = 0; i < c; i++) buf[i] = lst[i];
    for (int i = 1; i < c; i++) {
        int key = buf[i], k = i - 1;
        while (k >= 0 && buf[k] > key) { buf[k+1] = buf[k]; k--; }
        buf[k+1] = key;
    }
    for (int i = 0; i < c; i++) lst[i] = buf[i];
}

// ----------------------------------------------------------------------------
// fp32 SIMT split-K partial GEMM for init (exact). kChunk % 4 == 0.
// ----------------------------------------------------------------------------
#define BK 8
__global__ void __launch_bounds__(256)
gemm_part(const float* __restrict__ A, int lda,
          const float* __restrict__ W, int ldw,
          int K, int kChunk)
{
    __shared__ float As[BK][128 + 4];
    __shared__ float Ws[BK][128 + 4];
    const int z      = blockIdx.z;
    const int kStart = z * kChunk;
    const int kEnd   = min(kStart + kChunk, K);
    float* C = g_ipart + (long)z * NN * 128;

    const int tx   = threadIdx.x;
    const int row0 = blockIdx.y * 128;
    const int lm   = tx >> 1;
    const int lk4  = (tx & 1) << 2;
    const int tr   = (tx >> 4) << 3;
    const int tc   = (tx & 15) << 3;
    const bool alA = ((lda & 3) == 0);
    const bool alW = ((ldw & 3) == 0);

    float acc[8][8];
#pragma unroll
    for (int i = 0; i < 8; i++)
#pragma unroll
        for (int j = 0; j < 8; j++) acc[i][j] = 0.0f;

    const float* Ap = A + (long)(row0 + lm) * lda + lk4;
    const float* Wp = W + (long)lm * ldw + lk4;

    for (int k0 = kStart; k0 < kEnd; k0 += BK) {
        float a0, a1, a2, a3, w0, w1, w2, w3;
        if (alA && (k0 + lk4 + 3 < kEnd)) {
            float4 t = *reinterpret_cast<const float4*>(Ap + k0);
            a0 = t.x; a1 = t.y; a2 = t.z; a3 = t.w;
        } else {
            a0 = (k0 + lk4 + 0 < kEnd) ? Ap[k0 + 0] : 0.0f;
            a1 = (k0 + lk4 + 1 < kEnd) ? Ap[k0 + 1] : 0.0f;
            a2 = (k0 + lk4 + 2 < kEnd) ? Ap[k0 + 2] : 0.0f;
            a3 = (k0 + lk4 + 3 < kEnd) ? Ap[k0 + 3] : 0.0f;
        }
        if (alW && (k0 + lk4 + 3 < kEnd)) {
            float4 t = *reinterpret_cast<const float4*>(Wp + k0);
            w0 = t.x; w1 = t.y; w2 = t.z; w3 = t.w;
        } else {
            w0 = (k0 + lk4 + 0 < kEnd) ? Wp[k0 + 0] : 0.0f;
            w1 = (k0 + lk4 + 1 < kEnd) ? Wp[k0 + 1] : 0.0f;
            w2 = (k0 + lk4 + 2 < kEnd) ? Wp[k0 + 2] : 0.0f;
            w3 = (k0 + lk4 + 3 < kEnd) ? Wp[k0 + 3] : 0.0f;
        }
        __syncthreads();
        As[lk4 + 0][lm] = a0; As[lk4 + 1][lm] = a1;
        As[lk4 + 2][lm] = a2; As[lk4 + 3][lm] = a3;
        Ws[lk4 + 0][lm] = w0; Ws[lk4 + 1][lm] = w1;
        Ws[lk4 + 2][lm] = w2; Ws[lk4 + 3][lm] = w3;
        __syncthreads();
#pragma unroll
        for (int kk = 0; kk < BK; kk++) {
            float a[8], b[8];
            *reinterpret_cast<float4*>(&a[0]) = *reinterpret_cast<const float4*>(&As[kk][tr]);
            *reinterpret_cast<float4*>(&a[4]) = *reinterpret_cast<const float4*>(&As[kk][tr + 4]);
            *reinterpret_cast<float4*>(&b[0]) = *reinterpret_cast<const float4*>(&Ws[kk][tc]);
            *reinterpret_cast<float4*>(&b[4]) = *reinterpret_cast<const float4*>(&Ws[kk][tc + 4]);
#pragma unroll
            for (int i = 0; i < 8; i++)
#pragma unroll
                for (int j = 0; j < 8; j++)
                    acc[i][j] += a[i] * b[j];
        }
    }
#pragma unroll
    for (int i = 0; i < 8; i++) {
        int row = row0 + tr + i;
#pragma unroll
        for (int j = 0; j < 8; j++)
            C[(long)row * 128 + tc + j] = acc[i][j];
    }
}

// emb = tanh(sum of 4 partials + b_red); build g_init [N,144]
__global__ void concat_kernel(const float* __restrict__ states,
                              const float* __restrict__ sp,
                              const float* __restrict__ b_red) {
    int i = blockIdx.x * blockDim.x + threadIdx.x;
    if (i >= NN * 144) return;
    int n = i / 144, j = i % 144;
    float v;
    if (j < 128) {
        long o = (long)n * 128 + j;
        float s = b_red[j];
#pragma unroll
        for (int z = 0; z < 4; z++) s += g_ipart[(long)z * NN * 128 + o];
        v = tanhf(s);
    }
    else if (j < 138) v = states[n * 10 + (j - 128)];
    else              v = sp[n * 6 + (j - 138)];
    g_init[i] = v;
}

// h0 = tanh(sum of 2 partials + b_init); writes fp32 h and fp16 h16
__global__ void h0_kernel(const float* __restrict__ b_init, float* __restrict__ h) {
    int i = blockIdx.x * blockDim.x + threadIdx.x;
    if (i >= NN * 128) return;
    int j = i & 127;
    float v = tanhf(b_init[j] + g_ipart[i] + g_ipart[(long)NN * 128 + i]);
    h[i] = v;
    g_h16[i] = __float2half(v);
}

// ----------------------------------------------------------------------------
// HMMA GEMM with cp.async double-buffered mainloop.
// ----------------------------------------------------------------------------
__device__ __forceinline__ void ldsm4(uint32_t* r, uint32_t addr) {
    asm volatile("ldmatrix.sync.aligned.m8n8.x4.shared.b16 {%0,%1,%2,%3}, [%4];\n"
        : "=r"(r[0]), "=r"(r[1]), "=r"(r[2]), "=r"(r[3]) : "r"(addr));
}
__device__ __forceinline__ void mma16816(float* c, const uint32_t* a, const uint32_t* b) {
    asm volatile("mma.sync.aligned.m16n8k16.row.col.f32.f16.f16.f32 "
        "{%0,%1,%2,%3}, {%4,%5,%6,%7}, {%8,%9}, {%0,%1,%2,%3};\n"
        : "+f"(c[0]), "+f"(c[1]), "+f"(c[2]), "+f"(c[3])
        : "r"(a[0]), "r"(a[1]), "r"(a[2]), "r"(a[3]), "r"(b[0]), "r"(b[1]));
}

#define SLD 40                 // smem row stride in halves
#define STG_H (128 * SLD)      // halves per stage buffer

__device__ __forceinline__ void hgemm_main(
    __half* smem,
    const __half* __restrict__ A, int lda,
    const __half* __restrict__ Bm, int ldb,
    int K, int row0, int col0, float acc[4][4][4])
{
    const int tid  = threadIdx.x;
    const int lane = tid & 31;
    const int warp = tid >> 5;
    const int wr   = warp >> 2;
    const int wc   = warp & 3;

    __half* sA = smem;
    __half* sB = smem + 2 * STG_H;

    const uint32_t aBase = (uint32_t)__cvta_generic_to_shared(sA);
    const uint32_t bBase = (uint32_t)__cvta_generic_to_shared(sB);

    const int aRow  = (lane & 15);
    const int aKoff = (lane >> 4) << 3;
    const int bRow  = (lane & 7) | ((lane & 16) >> 1);
    const int bKoff = (lane & 8);

    const int r_  = tid >> 2;     // 0..63
    const int kc_ = tid & 3;

    auto load_stage = [&](int st, int k0) {
#pragma unroll
        for (int i = 0; i < 2; i++) {
            int r = r_ + (i << 6);
            __pipeline_memcpy_async(&sA[st * STG_H + r * SLD + kc_ * 8],
                                    &A[(long)(row0 + r) * lda + k0 + kc_ * 8], 16);
            __pipeline_memcpy_async(&sB[st * STG_H + r * SLD + kc_ * 8],
                                    &Bm[(long)(col0 + r) * ldb + k0 + kc_ * 8], 16);
        }
        __pipeline_commit();
    };

    const int KT = K >> 5;
    load_stage(0, 0);

    for (int kt = 0; kt < KT; kt++) {
        __pipeline_wait_prior(0);
        __syncthreads();
        if (kt + 1 < KT) load_stage((kt + 1) & 1, (kt + 1) << 5);
        const int st = kt & 1;
#pragma unroll
        for (int kk = 0; kk < 2; kk++) {
            uint32_t a[4][4], b[4][2];
#pragma unroll
            for (int mt = 0; mt < 4; mt++) {
                uint32_t addr = aBase + (uint32_t)((st * STG_H +
                    (wr * 64 + mt * 16 + aRow) * SLD + kk * 16 + aKoff) * 2);
                ldsm4(a[mt], addr);
            }
#pragma unroll
            for (int j = 0; j < 2; j++) {
                uint32_t r4[4];
                uint32_t addr = bBase + (uint32_t)((st * STG_H +
                    (wc * 32 + j * 16 + bRow) * SLD + kk * 16 + bKoff) * 2);
                ldsm4(r4, addr);
                b[2 * j][0]     = r4[0]; b[2 * j][1]     = r4[1];
                b[2 * j + 1][0] = r4[2]; b[2 * j + 1][1] = r4[3];
            }
#pragma unroll
            for (int mt = 0; mt < 4; mt++)
#pragma unroll
                for (int nt = 0; nt < 4; nt++)
                    mma16816(acc[mt][nt], a[mt], b[nt]);
        }
        __syncthreads();
    }
}

template<int ACT, typename OutT>
__global__ void __launch_bounds__(256)
hgemm(const __half* __restrict__ A, int lda,
      const __half* __restrict__ Bm, int ldb,
      const float* __restrict__ bias,
      OutT* __restrict__ C, int ldc, int K)
{
    __shared__ __half smem[4 * STG_H];
    const int lane = threadIdx.x & 31;
    const int warp = threadIdx.x >> 5;
    const int wr   = warp >> 2;
    const int wc   = warp & 3;
    const int row0 = blockIdx.y * 128;
    const int col0 = blockIdx.x * 128;

    float acc[4][4][4];
#pragma unroll
    for (int i = 0; i < 4; i++)
#pragma unroll
        for (int j = 0; j < 4; j++)
#pragma unroll
            for (int q = 0; q < 4; q++) acc[i][j][q] = 0.0f;

    hgemm_main(smem, A, lda, Bm, ldb, K, row0, col0, acc);

    const int g   = lane >> 2;
    const int tc2 = (lane & 3) << 1;
#pragma unroll
    for (int mt = 0; mt < 4; mt++) {
        int r0 = row0 + wr * 64 + mt * 16 + g;
#pragma unroll
        for (int nt = 0; nt < 4; nt++) {
            int col = col0 + wc * 32 + nt * 8 + tc2;
            float b0 = 0.f, b1 = 0.f;
            if (bias) { b0 = bias[col]; b1 = bias[col + 1]; }
            float v00 = acc[mt][nt][0] + b0, v01 = acc[mt][nt][1] + b1;
            float v10 = acc[mt][nt][2] + b0, v11 = acc[mt][nt][3] + b1;
            if (ACT == 1) { v00 = tanhf(v00); v01 = tanhf(v01);
                            v10 = tanhf(v10); v11 = tanhf(v11); }
            if constexpr (sizeof(OutT) == 2) {
                __half2 p0 = __floats2half2_rn(v00, v01);
                __half2 p1 = __floats2half2_rn(v10, v11);
                *reinterpret_cast<__half2*>(&C[(long)r0 * ldc + col])       = p0;
                *reinterpret_cast<__half2*>(&C[(long)(r0 + 8) * ldc + col]) = p1;
            } else {
                *reinterpret_cast<float2*>(&C[(long)r0 * ldc + col])       = make_float2(v00, v01);
                *reinterpret_cast<float2*>(&C[(long)(r0 + 8) * ldc + col]) = make_float2(v10, v11);
            }
        }
    }
}

// Fused gx(split-K=4) + gh launch. z 0..3: gx partial z (K=512); z==4: gh.
__global__ void __launch_bounds__(256) gxgh_kernel(const float* __restrict__ bh) {
    __shared__ __half smem[4 * STG_H];

    const int z = blockIdx.z;
    const __half* A;  const __half* Bm;
    const float* bias; float* C;
    int lda, ldb, K;
    if (z < 4) {
        A = g_msg16 + z * 512;  lda = MSGW;
        Bm = g_Wx16 + z * 512;  ldb = MSGW;
        C = g_gx + (long)z * NN * G3;
        bias = nullptr; K = 512;
    } else {
        A = g_h16;   lda = HH;
        Bm = g_Wh16; ldb = HH;
        C = g_gh;
        bias = bh; K = 128;
    }
    const int ldc = G3;
    const int lane = threadIdx.x & 31;
    const int warp = threadIdx.x >> 5;
    const int wr   = warp >> 2;
    const int wc   = warp & 3;
    const int row0 = blockIdx.y * 128;
    const int col0 = blockIdx.x * 128;

    float acc[4][4][4];
#pragma unroll
    for (int i = 0; i < 4; i++)
#pragma unroll
        for (int j = 0; j < 4; j++)
#pragma unroll
            for (int q = 0; q < 4; q++) acc[i][j][q] = 0.0f;

    hgemm_main(smem, A, lda, Bm, ldb, K, row0, col0, acc);

    const int g   = lane >> 2;
    const int tc2 = (lane & 3) << 1;
#pragma unroll
    for (int mt = 0; mt < 4; mt++) {
        int r0 = row0 + wr * 64 + mt * 16 + g;
#pragma unroll
        for (int nt = 0; nt < 4; nt++) {
            int col = col0 + wc * 32 + nt * 8 + tc2;
            float b0 = 0.f, b1 = 0.f;
            if (bias) { b0 = bias[col]; b1 = bias[col + 1]; }
            *reinterpret_cast<float2*>(&C[(long)r0 * ldc + col]) =
                make_float2(acc[mt][nt][0] + b0, acc[mt][nt][1] + b1);
            *reinterpret_cast<float2*>(&C[(long)(r0 + 8) * ldc + col]) =
                make_float2(acc[mt][nt][2] + b0, acc[mt][nt][3] + b1);
        }
    }
}

// ----------------------------------------------------------------------------
// SpMM (R11-proven): one warp per (dir,e,n) row; unroll 4.
// ----------------------------------------------------------------------------
__global__ void spmm_kernel() {
    int gw   = (blockIdx.x << 3) + (threadIdx.x >> 5);
    int lane = threadIdx.x & 31;
    int dir  = gw >> 15;
    int en   = gw & 32767;
    const int* ell = dir ? g_ell_in : g_ell_out;

    int c = g_cnt[dir * EE * NN + en];
    const int* lst = ell + (long)en * MAXW;
    int e = en >> 12;
    int n = en & 4095;
    int base = (dir << 10) + (e << 7);
    int fl   = (lane & 15) << 3;
    int s0   = lane >> 4;

    float acc[8];
#pragma unroll
    for (int j = 0; j < 8; j++) acc[j] = 0.f;

#pragma unroll 4
    for (int s = s0; s < c; s += 2) {
        int col = lst[s];
        int4 u = *reinterpret_cast<const int4*>(&g_hs16[(long)col * MSGW + base + fl]);
        const __half2* hp = reinterpret_cast<const __half2*>(&u);
#pragma unroll
        for (int j = 0; j < 4; j++) {
            float2 f = __half22float2(hp[j]);
            acc[2 * j]     += f.x;
            acc[2 * j + 1] += f.y;
        }
    }
#pragma unroll
    for (int j = 0; j < 8; j++)
        acc[j] += __shfl_down_sync(0xffffffffu, acc[j], 16);

    if (lane < 16) {
        __half2 o[4];
#pragma unroll
        for (int j = 0; j < 4; j++) o[j] = __floats2half2_rn(acc[2 * j], acc[2 * j + 1]);
        *reinterpret_cast<int4*>(&g_msg16[(long)n * MSGW + base + fl]) =
            *reinterpret_cast<const int4*>(o);
    }
}

// ----------------------------------------------------------------------------
// LayerNorm-GRU update. One block (128 threads) per node. Sums 4 gx partials.
// ----------------------------------------------------------------------------
__device__ __forceinline__ void stats128(float x, float* red, float& mean, float& var) {
    float s = x, q = x * x;
#pragma unroll
    for (int o = 16; o > 0; o >>= 1) {
        s += __shfl_xor_sync(0xffffffffu, s, o);
        q += __shfl_xor_sync(0xffffffffu, q, o);
    }
    int w = threadIdx.x >> 5;
    __syncthreads();
    if ((threadIdx.x & 31) == 0) { red[w] = s; red[4 + w] = q; }
    __syncthreads();
    s = red[0] + red[1] + red[2] + red[3];
    q = red[4] + red[5] + red[6] + red[7];
    mean = s * (1.0f / 128.0f);
    var  = q * (1.0f / 128.0f) - mean * mean;
}

__global__ void gru_kernel(const float* __restrict__ bx,
                           const float* __restrict__ gamma,
                           const float* __restrict__ beta,
                           float* __restrict__ h) {
    __shared__ float red[8];
    int n = blockIdx.x, j = threadIdx.x;
    const long rb = (long)n * G3;
    const long stride = (long)NN * G3;
    const float* ghr = g_gh + rb;

    float xr = bx[j], xz = bx[128 + j], xn = bx[256 + j];
#pragma unroll
    for (int z = 0; z < 4; z++) {
        const float* gxz = g_gx + (long)z * stride + rb;
        xr += gxz[j];
        xz += gxz[128 + j];
        xn += gxz[256 + j];
    }
    float hr = ghr[j], hz = ghr[128 + j], hn = ghr[256 + j];
    float hv = h[(long)n * 128 + j];

    float m, v;
    float ar = xr + hr;
    stats128(ar, red, m, v);
    float r = 1.0f / (1.0f + expf(-((ar - m) * rsqrtf(v + 1e-5f) * gamma[j] + beta[j])));

    float az = xz + hz;
    stats128(az, red, m, v);
    float z = 1.0f / (1.0f + expf(-((az - m) * rsqrtf(v + 1e-5f) * gamma[128 + j] + beta[128 + j])));

    float an = xn + r * hn;
    stats128(an, red, m, v);
    float nn = tanhf((an - m) * rsqrtf(v + 1e-5f) * gamma[256 + j] + beta[256 + j]);

    float hnew = (1.0f - z) * nn + z * hv;
    h[(long)n * 128 + j] = hnew;
    g_h16[(long)n * 128 + j] = __float2half(hnew);
}

// ----------------------------------------------------------------------------
// Host orchestration (single stream)
// ----------------------------------------------------------------------------
extern "C" void kernel_launch(void* const* d_in, const int* in_sizes, int n_in,
                              void* d_out, int out_size) {
    (void)in_sizes; (void)n_in; (void)out_size;
    const float* adj    = (const float*)d_in[0];
    const float* states = (const float*)d_in[1];
    const float* vecs   = (const float*)d_in[3];
    const float* sp     = (const float*)d_in[4];
    const float* W_red  = (const float*)d_in[5];
    const float* b_red  = (const float*)d_in[6];
    const float* W_init = (const float*)d_in[7];
    const float* b_init = (const float*)d_in[8];
    const float* W_out  = (const float*)d_in[9];
    const float* b_out  = (const float*)d_in[10];
    const float* W_in   = (const float*)d_in[11];
    const float* b_in   = (const float*)d_in[12];
    const float* Wx     = (const float*)d_in[13];
    const float* bx     = (const float*)d_in[14];
    const float* Wh     = (const float*)d_in[15];
    const float* bh     = (const float*)d_in[16];
    const float* gamma  = (const float*)d_in[17];
    const float* beta   = (const float*)d_in[18];
    float* h = (float*)d_out;

    float *p_init, *p_bcat;
    __half *p_hs, *p_h16, *p_Wcat;
    cudaGetSymbolAddress((void**)&p_init, g_init);
    cudaGetSymbolAddress((void**)&p_bcat, g_bcat);
    cudaGetSymbolAddress((void**)&p_hs,   g_hs16);
    cudaGetSymbolAddress((void**)&p_h16,  g_h16);
    cudaGetSymbolAddress((void**)&p_Wcat, g_Wcat16);

    // 1: fused build scan + weight packing
    buildprep_kernel<<<BUILD_BLOCKS + PREP_BLOCKS, 256>>>(
        adj, W_out, W_in, Wx, Wh, b_out, b_in);

    // 2: emb GEMM partials (split-K=4, aligned chunks)
    gemm_part<<<dim3(1, 32, 4), 256>>>(vecs, 300, W_red, 300, 300, 76);

    // 3: sort ELL rows + clamp counts + re-zero raw
    sort_kernel<<<2 * EE * NN / 256, 256>>>();

    // 4: emb tanh + concat -> g_init
    concat_kernel<<<(NN * 144 + 255) / 256, 256>>>(states, sp, b_red);

    // 5-6: h0 = tanh(init @ W_init^T + b_init)
    gemm_part<<<dim3(1, 32, 2), 256>>>(p_init, 144, W_init, 144, 144, 72);
    h0_kernel<<<(NN * 128 + 255) / 256, 256>>>(b_init, h);

    // ---- T message-passing + GRU steps ----
    for (int t = 0; t < TSTEPS; t++) {
        // hs = tanh(h @ Wcat^T + bcat)  -> fp16 [N,2048]   (pipelined)
        hgemm<1, __half><<<dim3(16, 32), 256>>>(p_h16, HH, p_Wcat, HH, p_bcat,
                                                p_hs, MSGW, HH);
        // sparse aggregation -> msg16 [N,2048]
        spmm_kernel<<<8192, 256>>>();
        // fused: gx partials (split-K=4) + gh (z=4), one launch (pipelined)
        gxgh_kernel<<<dim3(3, 32, 5), 256>>>(bh);
        // LayerNorm-GRU update (adds 4 gx partials + bx; writes h fp32 + h16)
        gru_kernel<<<NN, 128>>>(bx, gamma, beta, h);
    }
}